// round 1
// baseline (speedup 1.0000x reference)
#include <cuda_runtime.h>

// FourStateQuantizer: factorized soft quantization over 4 states {-1,-0.5,0.5,1},
// temp 0.3. Elementwise over all 50,331,648 floats.
//
// softmax(-(x-s_i)^2/T) weights: x^2 cancels -> w_i ∝ exp((2 s_i x - s_i^2)/T).
// With u = exp(x/T):
//   e(+1)  = c2 * u^2,  e(+0.5) = c1 * u,  e(-0.5) = c1 / u,  e(-1) = c2 / u^2
//   c1 = exp(-0.25/T), c2 = exp(-1/T)
// q = [c2 (u^2 - v^2) + 0.5 c1 (u - v)] / [c2 (u^2 + v^2) + c1 (u + v)],  v = 1/u.

__device__ __forceinline__ float quant1(float x) {
    // exp(x/0.3) = exp2(x * log2(e)/0.3)
    const float K  = 4.80898346962988f;      // 1.4426950408889634 / 0.3
    const float C1 = 0.4345982085070782f;    // exp(-0.25/0.3)
    const float C2 = 0.03567399334725241f;   // exp(-1.0/0.3)
    float u  = exp2f(x * K);                 // MUFU.EX2
    float v  = __frcp_rn(u);                 // MUFU.RCP
    float u2 = u * u;
    float v2 = v * v;
    float num = C2 * (u2 - v2) + 0.5f * C1 * (u - v);
    float den = C2 * (u2 + v2) + C1 * (u + v);
    return __fdividef(num, den);             // MUFU.RCP + FMUL (+NR)
}

__global__ __launch_bounds__(256) void fourstate_kernel(
    const float4* __restrict__ in, float4* __restrict__ out, int n4)
{
    int i = blockIdx.x * blockDim.x + threadIdx.x;
    if (i < n4) {
        float4 x = in[i];
        float4 q;
        q.x = quant1(x.x);
        q.y = quant1(x.y);
        q.z = quant1(x.z);
        q.w = quant1(x.w);
        out[i] = q;
    }
}

extern "C" void kernel_launch(void* const* d_in, const int* in_sizes, int n_in,
                              void* d_out, int out_size) {
    const float4* in = (const float4*)d_in[0];
    float4* out = (float4*)d_out;
    int n = in_sizes[0];          // 50,331,648 (divisible by 4)
    int n4 = n >> 2;              // 12,582,912
    int threads = 256;
    int blocks = (n4 + threads - 1) / threads;
    fourstate_kernel<<<blocks, threads>>>(in, out, n4);
}

// round 4
// speedup vs baseline: 1.1027x; 1.1027x over previous
#include <cuda_runtime.h>

// FourStateQuantizer: elementwise soft quantization over states {-1,-0.5,0.5,1}, T=0.3.
// softmax(-(x-s)^2/T): x^2 cancels -> w_i ∝ exp((2 s_i x - s_i^2)/T). With u = e^{x/T},
// multiply num/den by u^2 to get polynomials in u only (kills the 1/u MUFU.RCP):
//   q = [c2(u^4-1) + 0.5 c1 u(u^2-1)] / [c2(u^4+1) + c1 u(u^2+1)]
//   c1 = exp(-0.25/0.3), c2 = exp(-1/0.3)
// Clamp x to [-6,6]: q(±6) = ±(1 - 1.2e-8), and keeps u^4 = e^{4x/0.3} finite.
// 2 MUFU/elem (EX2 + RCP-divide), ~12 fp32 ops/elem.

__device__ __forceinline__ float quant1(float x) {
    const float K   = 4.80898346962988f;     // log2(e)/0.3
    const float C1H = 0.2172991042535391f;   // 0.5*exp(-0.25/0.3)
    const float C2  = 0.03567399334725241f;  // exp(-1.0/0.3)
    x = fminf(fmaxf(x, -6.0f), 6.0f);
    float u  = exp2f(x * K);                 // MUFU.EX2
    float u2 = u * u;
    float u4 = u2 * u2;
    float w1 = C1H * u;                      // 0.5*c1*u
    float w2 = w1 + w1;                      // c1*u
    float num = fmaf(w1, u2 - 1.0f, fmaf(C2, u4, -C2));
    float den = fmaf(w2, u2 + 1.0f, fmaf(C2, u4,  C2));
    return __fdividef(num, den);             // MUFU.RCP + FMUL
}

__device__ __forceinline__ float4 quant4(float4 x) {
    float4 q;
    q.x = quant1(x.x); q.y = quant1(x.y);
    q.z = quant1(x.z); q.w = quant1(x.w);
    return q;
}

// 4 float4 per thread, front-batched loads (MLP=4), batched stores.
__global__ __launch_bounds__(256) void fourstate_kernel(
    const float4* __restrict__ in, float4* __restrict__ out, int n4)
{
    int base = blockIdx.x * (256 * 4) + threadIdx.x;
    if (base + 3 * 256 < n4) {
        // fast path: all 4 in range (exact for this problem size)
        float4 x0 = in[base];
        float4 x1 = in[base + 256];
        float4 x2 = in[base + 512];
        float4 x3 = in[base + 768];
        float4 q0 = quant4(x0);
        float4 q1 = quant4(x1);
        float4 q2 = quant4(x2);
        float4 q3 = quant4(x3);
        out[base]       = q0;
        out[base + 256] = q1;
        out[base + 512] = q2;
        out[base + 768] = q3;
    } else {
        #pragma unroll
        for (int j = 0; j < 4; j++) {
            int i = base + j * 256;
            if (i < n4) out[i] = quant4(in[i]);
        }
    }
}

extern "C" void kernel_launch(void* const* d_in, const int* in_sizes, int n_in,
                              void* d_out, int out_size) {
    const float4* in = (const float4*)d_in[0];
    float4* out = (float4*)d_out;
    int n  = in_sizes[0];            // 50,331,648
    int n4 = n >> 2;                 // 12,582,912 float4s
    int per_block = 256 * 4;         // 1024 float4s per block
    int blocks = (n4 + per_block - 1) / per_block;  // 12288, exact
    fourstate_kernel<<<blocks, 256>>>(in, out, n4);
}